// round 17
// baseline (speedup 1.0000x reference)
#include <cuda_runtime.h>
#include <cuda_bf16.h>
#include <math.h>
#include <stdint.h>

// ---------------------------------------------------------------------------
// RandomProjection: out[b,o] = mean_s( cos(x[b,s,:], p[o,:]) )
// ONE fused kernel, grid 384 x 256 (all resident; spin barrier safe):
//   Phase A: blocks 0..127: x normalize+reduce -> g_part[4][32][768]
//            blocks 128..191: p-norms + bf16 pre-split (p*rpn) + zero(out)
//            blocks 192..383: straight to barrier
//   Barrier: monotonic ticket (release/acquire)
//   Phase B: all 384 blocks = 32 o-tiles x 12 k-splits:
//            bf16 3-term tensor GEMM (m16n8k16 + ldmatrix.x4),
//            m combine+split in staging, p pure copy, red.add.v2 epilogue
// ---------------------------------------------------------------------------

#define B_     32
#define S_     512
#define D_     768
#define O_     2048
#define EPS_   1e-8f

#define GRID   384
#define KSPLIT 12
#define KB     64            // k floats per gemm block
#define OTILE  64            // o rows per gemm block
#define PA     72            // bf16 smem pitch (144B rows, LDSM conflict-free)

__device__ float         g_part[4 * B_ * D_];   // x partials (race-free)
__device__ __nv_bfloat16 g_ph[O_ * D_];         // bf16 hi of p*rpn
__device__ __nv_bfloat16 g_pl[O_ * D_];         // bf16 lo
__device__ unsigned      g_bar;                 // monotonic barrier counter

// smem union: phase A tree (24576 B) / phase B tiles (27648 B)
#define SM_MH 0
#define SM_ML 4608
#define SM_PH 9216
#define SM_PL 18432
#define SM_BYTES 27648

// ---- bf16 split helpers -----------------------------------------------------
__device__ __forceinline__ void bf16_split(float v, __nv_bfloat16& h, __nv_bfloat16& l) {
    h = __float2bfloat16(v);
    l = __float2bfloat16(v - __bfloat162float(h));
}
__device__ __forceinline__ uint32_t pack2(__nv_bfloat16 lo, __nv_bfloat16 hi) {
    const __nv_bfloat162 t = __halves2bfloat162(lo, hi);   // x=lo (low 16b)
    return *reinterpret_cast<const uint32_t*>(&t);
}

// ---- ldmatrix / mma ----------------------------------------------------------
__device__ __forceinline__ void ldsm_x4(uint32_t* r, uint32_t addr) {
    asm volatile("ldmatrix.sync.aligned.m8n8.x4.shared.b16 {%0,%1,%2,%3}, [%4];"
                 : "=r"(r[0]), "=r"(r[1]), "=r"(r[2]), "=r"(r[3]) : "r"(addr));
}
__device__ __forceinline__ void mma_bf16(float* d, const uint32_t* a,
                                         uint32_t b0, uint32_t b1) {
    asm volatile(
        "mma.sync.aligned.m16n8k16.row.col.f32.bf16.bf16.f32 "
        "{%0,%1,%2,%3}, {%4,%5,%6,%7}, {%8,%9}, {%0,%1,%2,%3};"
        : "+f"(d[0]), "+f"(d[1]), "+f"(d[2]), "+f"(d[3])
        : "r"(a[0]), "r"(a[1]), "r"(a[2]), "r"(a[3]), "r"(b0), "r"(b1));
}

__global__ void __launch_bounds__(256, 3)
fused_kernel(const float* __restrict__ x, const float* __restrict__ p,
             float* __restrict__ out) {
    __shared__ __align__(16) uint8_t smem[SM_BYTES];

    const int tid  = threadIdx.x;
    const int warp = tid >> 5;
    const int lane = tid & 31;
    const int blk  = blockIdx.x;

    // ================= Phase A =================
    if (blk < 128) {
        // x reduce: block = (b = blk>>2, q = blk&3); 8 warps x 16 rows
        const int q = blk & 3;
        const int b = blk >> 2;
        const float4* base = reinterpret_cast<const float4*>(
            x + ((size_t)b * S_ + (size_t)q * 128 + (size_t)warp * 16) * D_);
        const float inv_S = 1.0f / (float)S_;

        float4 acc[6];
        #pragma unroll
        for (int c = 0; c < 6; c++) acc[c] = make_float4(0.f, 0.f, 0.f, 0.f);

        float4 v[6];
        #pragma unroll
        for (int c = 0; c < 6; c++) v[c] = base[lane + 32 * c];

        #pragma unroll
        for (int r = 0; r < 16; r++) {
            float4 vn[6];
            if (r < 15) {
                #pragma unroll
                for (int c = 0; c < 6; c++)
                    vn[c] = base[(r + 1) * 192 + lane + 32 * c];
            }
            float ss = 0.f;
            #pragma unroll
            for (int c = 0; c < 6; c++)
                ss += v[c].x * v[c].x + v[c].y * v[c].y
                    + v[c].z * v[c].z + v[c].w * v[c].w;
            #pragma unroll
            for (int off = 16; off > 0; off >>= 1)
                ss += __shfl_xor_sync(0xFFFFFFFFu, ss, off);

            const float scale = inv_S / fmaxf(sqrtf(ss), EPS_);
            #pragma unroll
            for (int c = 0; c < 6; c++) {
                acc[c].x += v[c].x * scale;
                acc[c].y += v[c].y * scale;
                acc[c].z += v[c].z * scale;
                acc[c].w += v[c].w * scale;
            }
            if (r < 15) {
                #pragma unroll
                for (int c = 0; c < 6; c++) v[c] = vn[c];
            }
        }

        float4* sm4 = reinterpret_cast<float4*>(smem);
        #pragma unroll
        for (int c = 0; c < 6; c++)
            sm4[warp * 192 + lane + 32 * c] = acc[c];
        __syncthreads();

        if (tid < 192) {
            float4 s = sm4[tid];
            #pragma unroll
            for (int w = 1; w < 8; w++) {
                const float4 t = sm4[w * 192 + tid];
                s.x += t.x; s.y += t.y; s.z += t.z; s.w += t.w;
            }
            reinterpret_cast<float4*>(g_part)[(q * B_ + b) * 192 + tid] = s;
        }
    } else if (blk < 192) {
        // p rows: 32 per block, 4 per warp: norm + scale + bf16 split; zero out
        const int pb = blk - 128;              // 0..63
        reinterpret_cast<float4*>(out)[pb * 256 + tid] =
            make_float4(0.f, 0.f, 0.f, 0.f);

        #pragma unroll
        for (int r = 0; r < 4; r++) {
            const int o = pb * 32 + warp * 4 + r;
            const float4* prow = reinterpret_cast<const float4*>(p + (size_t)o * D_);
            float4 v[6];
            float ss = 0.f;
            #pragma unroll
            for (int c = 0; c < 6; c++) {
                v[c] = prow[lane + 32 * c];
                ss += v[c].x * v[c].x + v[c].y * v[c].y
                    + v[c].z * v[c].z + v[c].w * v[c].w;
            }
            #pragma unroll
            for (int off = 16; off > 0; off >>= 1)
                ss += __shfl_xor_sync(0xFFFFFFFFu, ss, off);
            const float rp = 1.0f / fmaxf(sqrtf(ss), EPS_);

            #pragma unroll
            for (int c = 0; c < 6; c++) {
                __nv_bfloat16 h0, l0, h1, l1, h2, l2, h3, l3;
                bf16_split(v[c].x * rp, h0, l0);
                bf16_split(v[c].y * rp, h1, l1);
                bf16_split(v[c].z * rp, h2, l2);
                bf16_split(v[c].w * rp, h3, l3);
                const size_t off2 = (size_t)o * D_ + (lane + 32 * c) * 4;
                *reinterpret_cast<uint2*>(g_ph + off2) =
                    make_uint2(pack2(h0, h1), pack2(h2, h3));
                *reinterpret_cast<uint2*>(g_pl + off2) =
                    make_uint2(pack2(l0, l1), pack2(l2, l3));
            }
        }
    }
    // blocks 192..383: no phase-A work

    // ================= Grid barrier (monotonic ticket) =================
    __syncthreads();
    if (tid == 0) {
        __threadfence();                       // release phase-A writes
        const unsigned my = atomicAdd(&g_bar, 1u) + 1u;
        const unsigned target = ((my + GRID - 1u) / GRID) * GRID;
        unsigned cur;
        while (true) {
            asm volatile("ld.acquire.gpu.global.u32 %0, [%1];"
                         : "=r"(cur) : "l"(&g_bar));
            if ((int)(cur - target) >= 0) break;
            __nanosleep(64);
        }
    }
    __syncthreads();

    // ================= Phase B: bf16 3-term tensor GEMM =================
    const int kq = blk % KSPLIT;
    const int ot = blk / KSPLIT;               // 0..31
    const int k0 = kq * KB;

    __nv_bfloat16* mh = reinterpret_cast<__nv_bfloat16*>(smem + SM_MH);
    __nv_bfloat16* ml = reinterpret_cast<__nv_bfloat16*>(smem + SM_ML);
    __nv_bfloat16* ph = reinterpret_cast<__nv_bfloat16*>(smem + SM_PH);
    __nv_bfloat16* pl = reinterpret_cast<__nv_bfloat16*>(smem + SM_PL);

    // stage m: combine 4 partials + bf16 split; 512 positions, 2 per thread
    {
        const float4* gp = reinterpret_cast<const float4*>(g_part);
        #pragma unroll
        for (int t = 0; t < 2; t++) {
            const int i  = tid + t * 256;      // 0..511
            const int b  = i >> 4;             // 0..31
            const int kc = i & 15;             // 0..15
            const int col = kq * 16 + kc;
            float4 s = gp[(0 * B_ + b) * 192 + col];
            #pragma unroll
            for (int e = 1; e < 4; e++) {
                const float4 t4 = gp[(e * B_ + b) * 192 + col];
                s.x += t4.x; s.y += t4.y; s.z += t4.z; s.w += t4.w;
            }
            __nv_bfloat16 h0, l0, h1, l1, h2, l2, h3, l3;
            bf16_split(s.x, h0, l0); bf16_split(s.y, h1, l1);
            bf16_split(s.z, h2, l2); bf16_split(s.w, h3, l3);
            *reinterpret_cast<uint2*>(mh + b * PA + kc * 4) =
                make_uint2(pack2(h0, h1), pack2(h2, h3));
            *reinterpret_cast<uint2*>(ml + b * PA + kc * 4) =
                make_uint2(pack2(l0, l1), pack2(l2, l3));
        }
    }
    // stage p: pure uint4 copy (64 rows x 8 uint4 x 2 bufs = 1024, 4/thread)
    #pragma unroll
    for (int t = 0; t < 4; t++) {
        const int i   = tid + t * 256;         // 0..1023
        const int sel = i >> 9;                // 0: hi, 1: lo
        const int j   = i & 511;
        const int o   = j >> 3;                // 0..63
        const int kc8 = j & 7;                 // 0..7
        const size_t src = (size_t)(ot * OTILE + o) * D_ + k0 + kc8 * 8;
        const __nv_bfloat16* g = sel ? g_pl : g_ph;
        __nv_bfloat16* dst     = sel ? pl : ph;
        *reinterpret_cast<uint4*>(dst + o * PA + kc8 * 8) =
            *reinterpret_cast<const uint4*>(g + src);
    }
    __syncthreads();

    const int g    = lane >> 2;          // groupID 0..7
    const int tg   = lane & 3;           // threadID_in_group 0..3

    const int arow  = (lane & 7) + ((lane >> 3) & 1) * 8;   // + mt*16
    const int akseg = (lane >> 4) & 1;                      // * 8 elements
    const int brow  = warp * 8 + (lane & 7);                // N=8 rows
    const int bko   = (lane >> 3) * 8;                      // k-seg 0,8,16,24

    const uint32_t mh_u = (uint32_t)__cvta_generic_to_shared(mh);
    const uint32_t ml_u = (uint32_t)__cvta_generic_to_shared(ml);
    const uint32_t ph_u = (uint32_t)__cvta_generic_to_shared(ph);
    const uint32_t pl_u = (uint32_t)__cvta_generic_to_shared(pl);

    float d[2][4];
    #pragma unroll
    for (int mt = 0; mt < 2; mt++)
        #pragma unroll
        for (int r = 0; r < 4; r++) d[mt][r] = 0.f;

    #pragma unroll
    for (int ks = 0; ks < 2; ks++) {
        const int kb = ks * 32;

        uint32_t bh[4], bl[4];
        {
            const uint32_t off = (brow * PA + kb + bko) * 2;
            ldsm_x4(bh, ph_u + off);
            ldsm_x4(bl, pl_u + off);
        }

        #pragma unroll
        for (int half = 0; half < 2; half++) {
            const int kb16 = kb + half * 16;
            uint32_t ah[2][4], al[2][4];
            #pragma unroll
            for (int mt = 0; mt < 2; mt++) {
                const uint32_t off =
                    ((mt * 16 + arow) * PA + kb16 + akseg * 8) * 2;
                ldsm_x4(ah[mt], mh_u + off);
                ldsm_x4(al[mt], ml_u + off);
            }
            const uint32_t b0h = bh[2 * half], b1h = bh[2 * half + 1];
            const uint32_t b0l = bl[2 * half], b1l = bl[2 * half + 1];
            #pragma unroll
            for (int mt = 0; mt < 2; mt++) {
                mma_bf16(d[mt], ah[mt], b0h, b1h);   // hi*hi
                mma_bf16(d[mt], ah[mt], b0l, b1l);   // hi*lo
                mma_bf16(d[mt], al[mt], b0h, b1h);   // lo*hi
            }
        }
    }

    // epilogue
    const int col = ot * OTILE + warp * 8 + 2 * tg;
    #pragma unroll
    for (int mt = 0; mt < 2; mt++) {
        const int row = mt * 16 + g;
        float* dst0 = out + (size_t)row * O_ + col;
        float* dst1 = out + (size_t)(row + 8) * O_ + col;
        asm volatile("red.global.add.v2.f32 [%0], {%1, %2};"
                     :: "l"(dst0), "f"(d[mt][0]), "f"(d[mt][1]) : "memory");
        asm volatile("red.global.add.v2.f32 [%0], {%1, %2};"
                     :: "l"(dst1), "f"(d[mt][2]), "f"(d[mt][3]) : "memory");
    }
}

// ---------------------------------------------------------------------------
extern "C" void kernel_launch(void* const* d_in, const int* in_sizes, int n_in,
                              void* d_out, int out_size) {
    const float* x = (const float*)d_in[0];   // [32, 512, 768]
    const float* p = (const float*)d_in[1];   // [2048, 768]
    float*     out = (float*)d_out;           // [32, 2048]

    (void)in_sizes; (void)n_in; (void)out_size;

    fused_kernel<<<GRID, 256>>>(x, p, out);
}